// round 4
// baseline (speedup 1.0000x reference)
#include <cuda_runtime.h>
#include <math.h>

// Problem constants
#define Bq   64
#define Tq   256
#define Cq   2048
#define WEq  256
#define Hq   1024
#define G3q  3072
#define NBLK 144
#define NSPL 12

typedef unsigned long long u64;

// ---------------- scratch (device globals) -----------------------------------
__device__ float d_X  [Tq * Bq * WEq];
__device__ float d_gi [(size_t)Tq * G3q * Bq];   // TRANSPOSED: [t][n][b]
__device__ float d_H  [(Tq + 1) * Bq * Hq];      // [t][b][j]
__device__ float d_ghp[NSPL * G3q * Bq];         // [split][n][b]
__device__ float d_e  [Tq * Bq * Tq];
__device__ float d_ctx[(size_t)Tq * Bq * Hq];
__device__ int      d_words[Bq];
__device__ unsigned g_barx[8 * 32];              // padded barrier sub-counters
__device__ unsigned g_exit;

// ---------------- f32x2 helpers ----------------------------------------------
__device__ __forceinline__ void ffma2(u64& d, u64 a, u64 b) {
    asm("fma.rn.f32x2 %0, %1, %2, %0;" : "+l"(d) : "l"(a), "l"(b));
}
__device__ __forceinline__ float2 u2f2(u64 v) {
    unsigned lo, hi;
    asm("mov.b64 {%0, %1}, %2;" : "=r"(lo), "=r"(hi) : "l"(v));
    return make_float2(__uint_as_float(lo), __uint_as_float(hi));
}

// ============================================================================
// Bulk f32x2 GEMM: 256 threads, BM=256, BN=128, per-thread 16m x 8n.
// C[m,n] = sum_k A[m,k]*B[n,k] + bias[n].  Optional concat-A (A2 from k>=K1).
// mode 0: C row m (ldc).  mode 1: row (m&63)*Tq + (m>>6).  mode 2 (transpose):
//   addr = ((m>>6)*G3q + n)*64 + (m&63), pair stored as float2.
// BNC=true: B element (n,k) at k*ldb + n.
// ============================================================================
template <bool BNC>
__global__ __launch_bounds__(256, 1) void gemmX_k(
    const float* __restrict__ A, const float* __restrict__ A2, int K1,
    const float* __restrict__ Bm, float* __restrict__ Cm, int K,
    int lda, int ldb, int ldc,
    long long a_bs, long long b_bs, long long c_bs,
    const float* __restrict__ bias, int mode)
{
    __shared__ __align__(16) float As[16 * 256];
    __shared__ __align__(16) float Bs[16 * 256];   // duplicated pairs: [k][2*128]

    const int tid = threadIdx.x;
    const int tx  = tid & 15;           // n group
    const int ty  = tid >> 4;           // m group (16 rows each)
    const int n0  = blockIdx.x * 128;
    const int m0  = blockIdx.y * 256;

    const float* Ab  = A  + (size_t)blockIdx.z * a_bs;
    const float* Bb  = Bm + (size_t)blockIdx.z * b_bs;
    float*       Cb  = Cm + (size_t)blockIdx.z * c_bs;

    const float* rowA  = Ab + (size_t)(m0 + tid) * lda;
    const float* rowA2 = A2 ? (A2 + (size_t)blockIdx.z * a_bs + (size_t)(m0 + tid) * lda) : nullptr;

    // B load mapping
    const int bn  = tid & 127;          // !BNC
    const int bkc = tid >> 7;           // 0..1
    const int n4  = tid & 31;           // BNC
    const int kr  = tid >> 5;           // 0..7
    const float* rowB = Bb + (size_t)(n0 + bn) * ldb + bkc * 4;

    u64 acc[8][8];
#pragma unroll
    for (int p = 0; p < 8; p++)
#pragma unroll
        for (int j = 0; j < 8; j++) acc[p][j] = 0ull;

    float4 a_r[4], b_r[2];

    auto LOADA = [&](int kt) {
#pragma unroll
        for (int i = 0; i < 4; i++) {
            int k = kt * 16 + 4 * i;
            const float* p = (rowA2 && k >= K1) ? (rowA2 + (k - K1)) : (rowA + k);
            a_r[i] = *(const float4*)p;
        }
    };
    auto LOADB = [&](int kt) {
        if (!BNC) {
#pragma unroll
            for (int i = 0; i < 2; i++)
                b_r[i] = *(const float4*)(rowB + kt * 16 + 8 * i);
        } else {
#pragma unroll
            for (int i = 0; i < 2; i++)
                b_r[i] = *(const float4*)(Bb + (size_t)(kt * 16 + kr + 8 * i) * ldb + n0 + n4 * 4);
        }
    };
    auto STORE = [&]() {
#pragma unroll
        for (int i = 0; i < 4; i++) {
            As[(4 * i + 0) * 256 + tid] = a_r[i].x;
            As[(4 * i + 1) * 256 + tid] = a_r[i].y;
            As[(4 * i + 2) * 256 + tid] = a_r[i].z;
            As[(4 * i + 3) * 256 + tid] = a_r[i].w;
        }
        if (!BNC) {
#pragma unroll
            for (int i = 0; i < 2; i++) {
                int kb = 4 * (bkc + 2 * i);
                float* q = &Bs[kb * 256 + 2 * bn];
                q[0] = b_r[i].x; q[1] = b_r[i].x;
                q[256] = b_r[i].y; q[257] = b_r[i].y;
                q[512] = b_r[i].z; q[513] = b_r[i].z;
                q[768] = b_r[i].w; q[769] = b_r[i].w;
            }
        } else {
#pragma unroll
            for (int i = 0; i < 2; i++) {
                int k = kr + 8 * i;
                float* q = &Bs[k * 256 + 8 * n4];
                q[0] = b_r[i].x; q[1] = b_r[i].x;
                q[2] = b_r[i].y; q[3] = b_r[i].y;
                q[4] = b_r[i].z; q[5] = b_r[i].z;
                q[6] = b_r[i].w; q[7] = b_r[i].w;
            }
        }
    };

    LOADA(0); LOADB(0);
    const int nt = K / 16;
    for (int it = 0; it < nt; it++) {
        __syncthreads();
        STORE();
        __syncthreads();
        if (it + 1 < nt) { LOADA(it + 1); LOADB(it + 1); }

#pragma unroll
        for (int k = 0; k < 16; k++) {
            const float* bsk = &Bs[k * 256 + 2 * tx];
            const float* ask = &As[k * 256 + ty * 16];
            u64 bv[8];
#pragma unroll
            for (int j = 0; j < 8; j++) bv[j] = *(const u64*)(bsk + 32 * j);
            u64 av[8];
#pragma unroll
            for (int p = 0; p < 8; p++) av[p] = *(const u64*)(ask + 2 * p);
#pragma unroll
            for (int p = 0; p < 8; p++)
#pragma unroll
                for (int j = 0; j < 8; j++)
                    ffma2(acc[p][j], av[p], bv[j]);
        }
    }

    // epilogue
    float bj[8];
#pragma unroll
    for (int j = 0; j < 8; j++)
        bj[j] = bias ? bias[n0 + j * 16 + tx] : 0.f;

#pragma unroll
    for (int p = 0; p < 8; p++) {
        int mA = m0 + ty * 16 + 2 * p;
        if (mode == 2) {
            float* base = Cb + ((size_t)(mA >> 6) * G3q) * 64 + (mA & 63);
#pragma unroll
            for (int j = 0; j < 8; j++) {
                float2 f = u2f2(acc[p][j]);
                f.x += bj[j]; f.y += bj[j];
                int n = n0 + j * 16 + tx;
                *(float2*)(base + (size_t)n * 64) = f;
            }
        } else {
            size_t rA, rB;
            if (mode == 1) {
                rA = (size_t)(mA & 63) * Tq + (mA >> 6);
                rB = (size_t)((mA + 1) & 63) * Tq + ((mA + 1) >> 6);
            } else {
                rA = (size_t)mA; rB = (size_t)mA + 1;
            }
            float* cpa = Cb + rA * (size_t)ldc + n0;
            float* cpb = Cb + rB * (size_t)ldc + n0;
#pragma unroll
            for (int j = 0; j < 8; j++) {
                float2 f = u2f2(acc[p][j]);
                int off = j * 16 + tx;
                cpa[off] = f.x + bj[j];
                cpb[off] = f.y + bj[j];
            }
        }
    }
}

// ============================================================================
// Persistent GRU recurrence: one launch, 256 steps, software grid barriers.
// 144 blocks x 128 threads, each owns a (256n x ~85k) slice of W_hh staged
// ONCE into smem (duplicated pairs). Per step: gh partials -> barrier ->
// fused gates -> barrier.
// ============================================================================
__device__ __forceinline__ void gridbar(unsigned target)
{
    __syncthreads();
    if (threadIdx.x == 0) {
        __threadfence();
        atomicAdd(&g_barx[(blockIdx.x & 7) * 32], 1u);
        unsigned s;
        do {
            s = 0;
#pragma unroll
            for (int i = 0; i < 8; i++)
                s += *(volatile unsigned*)&g_barx[i * 32];
        } while (s < target);
        __threadfence();
    }
    __syncthreads();
}

__global__ __launch_bounds__(128, 1) void gru_persist_k(
    const float* __restrict__ W_hh, const float* __restrict__ b_hh)
{
    extern __shared__ float sm[];
    float* Bs = sm;               // [klen][512]  (dup pairs), max 88*512
    float* As = sm + 88 * 512;    // [klen][64],  max 88*64

    const int tid = threadIdx.x;
    const int bid = blockIdx.x;
    const int ks  = bid / NSPL ? 0 : 0;  // placeholder (overwritten below)
    (void)ks;
    const int spl = bid / NSPL;          // 0..11  k-split
    const int nt  = bid % NSPL;          // 0..11  n-tile
    const int cnt = (spl < 8) ? 11 : 10;            // BK=8 tiles
    const int k0  = ((spl < 8) ? 11 * spl : 88 + 10 * (spl - 8)) * 8;
    const int klen = cnt * 8;
    const int n0  = nt * 256;

    // ---- stage W_hh slice into smem (once), duplicated pairs ----
    const int kq = klen / 4;
    for (int idx = tid; idx < 256 * kq; idx += 128) {
        int n = idx / kq, c4 = idx % kq;
        float4 v = *(const float4*)(W_hh + (size_t)(n0 + n) * Hq + k0 + 4 * c4);
        float* q = Bs + (4 * c4) * 512 + 2 * n;
        q[0]    = v.x; q[1]    = v.x;
        q[512]  = v.y; q[513]  = v.y;
        q[1024] = v.z; q[1025] = v.z;
        q[1536] = v.w; q[1537] = v.w;
    }

    const int ty = tid >> 5;   // 0..3  (m base ty*16)
    const int tx = tid & 31;   // n = tx + 32*j

    unsigned barid = 0;

    for (int t = 0; t < Tq; t++) {
        const float* Ht = d_H + (size_t)t * Bq * Hq;

        // ---- stage A = H_t[:, k-range] ----
        __syncthreads();   // protect As vs previous compute readers
        for (int idx = tid; idx < 64 * kq; idx += 128) {
            int r = idx / kq, c4 = idx % kq;
            float4 v = *(const float4*)(Ht + (size_t)r * Hq + k0 + 4 * c4);
            As[(4 * c4 + 0) * 64 + r] = v.x;
            As[(4 * c4 + 1) * 64 + r] = v.y;
            As[(4 * c4 + 2) * 64 + r] = v.z;
            As[(4 * c4 + 3) * 64 + r] = v.w;
        }
        __syncthreads();

        // ---- gh partial: 64 x 256 tile, K = klen ----
        u64 acc[8][8];
#pragma unroll
        for (int p = 0; p < 8; p++)
#pragma unroll
            for (int j = 0; j < 8; j++) acc[p][j] = 0ull;

#pragma unroll 2
        for (int k = 0; k < klen; k++) {
            const float* ask = As + k * 64 + ty * 16;
            const float* bsk = Bs + k * 512 + 2 * tx;
            u64 bv[8];
#pragma unroll
            for (int j = 0; j < 8; j++) bv[j] = *(const u64*)(bsk + 64 * j);
            u64 av[8];
#pragma unroll
            for (int p = 0; p < 8; p++) av[p] = *(const u64*)(ask + 2 * p);
#pragma unroll
            for (int p = 0; p < 8; p++)
#pragma unroll
                for (int j = 0; j < 8; j++)
                    ffma2(acc[p][j], av[p], bv[j]);
        }

        // write partials: d_ghp[spl][n][b], pair (b, b+1) contiguous
        {
            float* gp = d_ghp + ((size_t)spl * G3q + n0) * 64;
#pragma unroll
            for (int j = 0; j < 8; j++) {
                int n = 32 * j + tx;
#pragma unroll
                for (int p = 0; p < 8; p++) {
                    int m = ty * 16 + 2 * p;
                    *(u64*)(gp + (size_t)n * 64 + m) = acc[p][j];
                }
            }
        }

        gridbar(NBLK * (++barid));

        // ---- fused gates: h_{t+1} ----
        const float* git = d_gi + (size_t)t * G3q * 64;   // [n][b]
        for (int idx = bid * 128 + tid; idx < Bq * Hq; idx += NBLK * 128) {
            int b = idx & 63, j = idx >> 6;
            float sr = b_hh[j], sz = b_hh[Hq + j], sn = b_hh[2 * Hq + j];
#pragma unroll
            for (int s = 0; s < NSPL; s++) {
                const float* q = d_ghp + (size_t)s * G3q * 64;
                sr += q[(size_t)j * 64 + b];
                sz += q[(size_t)(Hq + j) * 64 + b];
                sn += q[(size_t)(2 * Hq + j) * 64 + b];
            }
            float gir = git[(size_t)j * 64 + b];
            float giz = git[(size_t)(Hq + j) * 64 + b];
            float gin = git[(size_t)(2 * Hq + j) * 64 + b];
            float r = 1.f / (1.f + expf(-(gir + sr)));
            float z = 1.f / (1.f + expf(-(giz + sz)));
            float nn = tanhf(gin + r * sn);
            float hp = Ht[(size_t)b * Hq + j];
            d_H[((size_t)(t + 1) * Bq + b) * Hq + j] = (1.f - z) * nn + z * hp;
        }
        __threadfence();
        gridbar(NBLK * (++barid));
    }

    // ---- exit protocol: reset counters deterministically ----
    __syncthreads();
    if (tid == 0) {
        atomicAdd(&g_exit, 1u);
        if (bid == 0) {
            while (*(volatile unsigned*)&g_exit < NBLK) {}
#pragma unroll
            for (int i = 0; i < 8; i++) g_barx[i * 32] = 0u;
            g_exit = 0u;
            __threadfence();
        }
    }
}

// ---------------- small kernels ----------------------------------------------
__global__ void embed_k(const int* __restrict__ targets, const float* __restrict__ E)
{
    int m = blockIdx.x;                 // t*B + b
    int t = m >> 6, b = m & 63;
    int id = (t == 0) ? 0 : targets[b * Tq + (t - 1)];
    const float4* src = (const float4*)(E + (size_t)id * WEq);
    float4* dst = (float4*)(d_X + (size_t)m * WEq);
    dst[threadIdx.x] = src[threadIdx.x];
}

__global__ void words_k(const unsigned char* __restrict__ mask8)
{
    int b = blockIdx.x, t = threadIdx.x;
    int is8 = (mask8[1] != 0);
    int v;
    if (is8) v = mask8[b * Tq + t] ? 1 : 0;
    else     v = ((const int*)mask8)[b * Tq + t] ? 1 : 0;
#pragma unroll
    for (int o = 16; o; o >>= 1) v += __shfl_down_sync(0xffffffffu, v, o);
    __shared__ int red[8];
    if ((t & 31) == 0) red[t >> 5] = v;
    __syncthreads();
    if (t == 0) {
        int s = 0;
#pragma unroll
        for (int i = 0; i < 8; i++) s += red[i];
        d_words[b] = s;
    }
}

__global__ void h0_k(const float* __restrict__ enc)
{
    int b = blockIdx.x;
    const float4* src = (const float4*)(enc + ((size_t)b * Tq + (Tq - 1)) * Hq);
    float4* dst = (float4*)(d_H + (size_t)b * Hq);
    dst[threadIdx.x] = src[threadIdx.x];
}

__global__ void softmax_k()
{
    int m = blockIdx.x;                 // t*B + b
    int b = m & (Bq - 1);
    int wn = d_words[b];
    float* e = d_e + (size_t)m * Tq;
    int s = threadIdx.x;
    float v = (s < wn) ? e[s] : -3.0e38f;

    __shared__ float red[8];
    __shared__ float smax, ssum;
    float mx = v;
#pragma unroll
    for (int o = 16; o; o >>= 1) mx = fmaxf(mx, __shfl_xor_sync(0xffffffffu, mx, o));
    if ((s & 31) == 0) red[s >> 5] = mx;
    __syncthreads();
    if (s == 0) {
        float x = red[0];
#pragma unroll
        for (int i = 1; i < 8; i++) x = fmaxf(x, red[i]);
        smax = x;
    }
    __syncthreads();
    float ex = (s < wn) ? expf(v - smax) : 0.f;
    float sum = ex;
#pragma unroll
    for (int o = 16; o; o >>= 1) sum += __shfl_xor_sync(0xffffffffu, sum, o);
    if ((s & 31) == 0) red[s >> 5] = sum;
    __syncthreads();
    if (s == 0) {
        float x = 0.f;
#pragma unroll
        for (int i = 0; i < 8; i++) x += red[i];
        ssum = 1.f / x;
    }
    __syncthreads();
    e[s] = ex * ssum;
}

// ---------------- launch ------------------------------------------------------
extern "C" void kernel_launch(void* const* d_in, const int* in_sizes, int n_in,
                              void* d_out, int out_size)
{
    const float*         enc     = (const float*)d_in[0];
    const unsigned char* mask    = (const unsigned char*)d_in[1];
    const int*           targets = (const int*)d_in[2];
    const float*         E       = (const float*)d_in[3];
    const float*         W_ih    = (const float*)d_in[4];
    const float*         W_hh    = (const float*)d_in[5];
    const float*         b_ih    = (const float*)d_in[6];
    const float*         b_hh    = (const float*)d_in[7];
    const float*         W_out   = (const float*)d_in[8];
    const float*         b_out   = (const float*)d_in[9];
    float* out = (float*)d_out;

    void* p;
    cudaGetSymbolAddress(&p, d_X);   float* X   = (float*)p;
    cudaGetSymbolAddress(&p, d_gi);  float* GI  = (float*)p;
    cudaGetSymbolAddress(&p, d_H);   float* Hh  = (float*)p;
    cudaGetSymbolAddress(&p, d_e);   float* Ee  = (float*)p;
    cudaGetSymbolAddress(&p, d_ctx); float* CTX = (float*)p;

    static int smem_set = 0;
    if (!smem_set) {
        cudaFuncSetAttribute(gru_persist_k,
                             cudaFuncAttributeMaxDynamicSharedMemorySize, 202752);
        smem_set = 1;
    }

    // Phase 0
    embed_k<<<Tq * Bq, 64>>>(targets, E);
    words_k<<<Bq, 256>>>(mask);
    h0_k<<<Bq, 256>>>(enc);

    // Phase 1: gi = X @ W_ih^T + b_ih, written TRANSPOSED [t][n][b] (mode 2)
    gemmX_k<false><<<dim3(G3q / 128, (Tq * Bq) / 256, 1), 256>>>(
        X, nullptr, 0, W_ih, GI, WEq, WEq, WEq, 0, 0, 0, 0, b_ih, 2);

    // Phase 2: persistent GRU recurrence (single launch, 256 steps)
    gru_persist_k<<<NBLK, 128, 202752>>>(W_hh, b_hh);

    // Phase 3a: e[t,b,s] = h1[t,b,:] . enc[b,s,:]
    gemmX_k<false><<<dim3(Tq / 128, 1, Bq), 256>>>(
        Hh + (size_t)Bq * Hq, nullptr, 0, enc, Ee, Hq,
        Bq * Hq, Hq, Bq * Tq,
        Hq, (long long)Tq * Hq, Tq,
        nullptr, 0);

    // Phase 3b: masked softmax
    softmax_k<<<Tq * Bq, Tq>>>();

    // Phase 3c: ctx[t,b,:] = alpha[t,b,:] @ enc[b]   (B n-contiguous)
    gemmX_k<true><<<dim3(Hq / 128, 1, Bq), 256>>>(
        Ee, nullptr, 0, enc, CTX, Tq,
        Bq * Tq, Hq, Bq * Hq,
        Tq, (long long)Tq * Hq, Hq,
        nullptr, 0);

    // Phase 4: logits = [h1 | ctx] @ W_out^T + b_out, K=2048 concat, (B,T,C) out
    gemmX_k<false><<<dim3(Cq / 128, (Tq * Bq) / 256, 1), 256>>>(
        Hh + (size_t)Bq * Hq, CTX, Hq, W_out, out, 2 * Hq,
        Hq, 2 * Hq, Cq, 0, 0, 0, b_out, 1);
}

// round 5
// speedup vs baseline: 1.0643x; 1.0643x over previous
#include <cuda_runtime.h>
#include <math.h>

// Problem constants
#define Bq   64
#define Tq   256
#define Cq   2048
#define WEq  256
#define Hq   1024
#define G3q  3072
#define SPLITS 8
#define BK   16

typedef unsigned long long u64;

// ---------------- scratch (device globals) -----------------------------------
__device__ float d_X  [Tq * Bq * WEq];
__device__ float d_gi [(size_t)Tq * Bq * G3q];   // [t][b][n]
__device__ float d_H  [(Tq + 1) * Bq * Hq];      // [t][b][j]
__device__ float d_ghp[SPLITS * Bq * G3q];       // [split][b][n]
__device__ float d_e  [Tq * Bq * Tq];
__device__ float d_ctx[(size_t)Tq * Bq * Hq];
__device__ int   d_words[Bq];

// ---------------- f32x2 helpers ----------------------------------------------
__device__ __forceinline__ void ffma2(u64& d, u64 a, u64 b) {
    asm("fma.rn.f32x2 %0, %1, %2, %0;" : "+l"(d) : "l"(a), "l"(b));
}
__device__ __forceinline__ float2 u2f2(u64 v) {
    unsigned lo, hi;
    asm("mov.b64 {%0, %1}, %2;" : "=r"(lo), "=r"(hi) : "l"(v));
    return make_float2(__uint_as_float(lo), __uint_as_float(hi));
}
__device__ __forceinline__ u64 pack2(float x) {
    u64 r;
    asm("mov.b64 %0, {%1, %1};" : "=l"(r) : "f"(x));
    return r;
}

// ---------------- f32x2 GEMM, pairs along M, B un-duplicated ------------------
// C[m, n] (+=bias) = sum_k A[m, k] * B[n, k]
// A: row m k-contiguous (lda). Optional concat: k >= K1 reads A2 (same lda).
// B !BNC: row n k-contiguous (ldb). B BNC: element (n,k) at k*ldb + n.
// blockIdx.z batching via a_bs/b_bs/c_bs.
// mode 0: C row = m. mode 1: C row = (m&63)*Tq + (m>>6)   (t*B+b -> b*T+t).
// Per-thread tile TM x TN; A smem natural (LDS.64 = m-pair); B smem scalar,
// duplicated into {b,b} via mov.b64 at compute time (ALU pipe).
template <int BM, int BN, int TM, int TN, bool BNC>
__global__ __launch_bounds__((BM / TM) * (BN / TN), 2) void gemm2_k(
    const float* __restrict__ A, const float* __restrict__ A2, int K1,
    const float* __restrict__ Bm, float* __restrict__ Cm, int K,
    int lda, int ldb, int ldc,
    long long a_bs, long long b_bs, long long c_bs,
    const float* __restrict__ bias, int accf, int mode)
{
    constexpr int THREADS = (BM / TM) * (BN / TN);
    constexpr int NTX = BN / TN;          // threads along n
    constexpr int NP  = TM / 2;           // m-pairs per thread
    constexpr int NA4 = (BM * BK) / (4 * THREADS);
    constexpr int NB4 = (BN * BK) / (4 * THREADS);
    constexpr int PA  = THREADS / BM;
    constexpr int PB  = THREADS / BN;

    __shared__ __align__(16) float As[2][BK][BM];
    __shared__ __align__(16) float Bs[2][BK][BN];

    const int tid = threadIdx.x;
    const int tx  = tid % NTX;
    const int ty  = tid / NTX;
    const int n0  = blockIdx.x * BN;
    const int m0  = blockIdx.y * BM;
    const float* Ab  = A  + (size_t)blockIdx.z * a_bs;
    const float* A2b = A2 ? (A2 + (size_t)blockIdx.z * a_bs) : nullptr;
    const float* Bb  = Bm + (size_t)blockIdx.z * b_bs;
    float*       Cb  = Cm + (size_t)blockIdx.z * c_bs;

    // global load mappings
    const int ar  = tid % BM;
    const int akc = tid / BM;
    const float* Ap  = Ab + (size_t)(m0 + ar) * lda + akc * 4;
    const float* Ap2 = A2b ? (A2b + (size_t)(m0 + ar) * lda + akc * 4) : nullptr;

    int bn = 0, bkc = 0, bkr = 0, bn4 = 0;
    const float* Bp;
    if (!BNC) {
        bn  = tid % BN;
        bkc = tid / BN;
        Bp  = Bb + (size_t)(n0 + bn) * ldb + bkc * 4;
    } else {
        bkr = tid >> 5;            // 0..3
        bn4 = (tid & 31) * 4;      // 0..124
        Bp  = Bb + (size_t)bkr * ldb + n0 + bn4;
    }

    u64 acc[NP][TN];
#pragma unroll
    for (int p = 0; p < NP; p++)
#pragma unroll
        for (int j = 0; j < TN; j++) acc[p][j] = 0ull;

    float4 a_r[NA4], b_r[NB4];

    auto LOADA = [&](int kt) {
#pragma unroll
        for (int i = 0; i < NA4; i++) {
            int k = kt * BK + akc * 4 + 4 * i * PA - akc * 4;  // base col offset
            int kcol = kt * BK + 4 * i * PA;
            const float* base = (Ap2 && (kcol + akc * 4) >= K1)
                              ? (Ap2 - K1) : Ap;
            a_r[i] = *(const float4*)(base + kcol);
            (void)k;
        }
    };
    auto LOADB = [&](int kt) {
        if (!BNC) {
#pragma unroll
            for (int i = 0; i < NB4; i++)
                b_r[i] = *(const float4*)(Bp + (size_t)kt * BK + 4 * i * PB);
        } else {
#pragma unroll
            for (int i = 0; i < NB4; i++)
                b_r[i] = *(const float4*)(Bp + (size_t)(kt * BK + 4 * i) * ldb);
        }
    };
    auto STORE = [&](int buf) {
#pragma unroll
        for (int i = 0; i < NA4; i++) {
            int k4 = akc + i * PA;
            As[buf][4 * k4 + 0][ar] = a_r[i].x;
            As[buf][4 * k4 + 1][ar] = a_r[i].y;
            As[buf][4 * k4 + 2][ar] = a_r[i].z;
            As[buf][4 * k4 + 3][ar] = a_r[i].w;
        }
        if (!BNC) {
#pragma unroll
            for (int i = 0; i < NB4; i++) {
                int k4 = bkc + i * PB;
                Bs[buf][4 * k4 + 0][bn] = b_r[i].x;
                Bs[buf][4 * k4 + 1][bn] = b_r[i].y;
                Bs[buf][4 * k4 + 2][bn] = b_r[i].z;
                Bs[buf][4 * k4 + 3][bn] = b_r[i].w;
            }
        } else {
#pragma unroll
            for (int i = 0; i < NB4; i++) {
                int k = bkr + 4 * i;
                *(float4*)&Bs[buf][k][bn4] = b_r[i];
            }
        }
    };

    LOADA(0); LOADB(0);
    STORE(0);
    __syncthreads();

    const int nt = K / BK;
    for (int it = 0; it < nt; it++) {
        const int cur = it & 1;
        if (it + 1 < nt) { LOADA(it + 1); LOADB(it + 1); }

#pragma unroll
        for (int k = 0; k < BK; k++) {
            const float* ask = &As[cur][k][ty * TM];
            const float* bsk = &Bs[cur][k][tx];
            u64 bv[TN];
#pragma unroll
            for (int j = 0; j < TN; j++)
                bv[j] = pack2(bsk[j * NTX]);
            u64 av[NP];
#pragma unroll
            for (int p = 0; p < NP; p++)
                av[p] = *(const u64*)(ask + 2 * p);
#pragma unroll
            for (int p = 0; p < NP; p++)
#pragma unroll
                for (int j = 0; j < TN; j++)
                    ffma2(acc[p][j], av[p], bv[j]);
        }

        if (it + 1 < nt) STORE(cur ^ 1);
        __syncthreads();
    }

    // epilogue
    float bj[TN];
#pragma unroll
    for (int j = 0; j < TN; j++)
        bj[j] = bias ? bias[n0 + j * NTX + tx] : 0.f;

#pragma unroll
    for (int p = 0; p < NP; p++) {
        int mA = m0 + ty * TM + 2 * p;
        int mB = mA + 1;
        size_t rA = (mode == 1) ? ((size_t)(mA & 63) * Tq + (mA >> 6)) : (size_t)mA;
        size_t rB = (mode == 1) ? ((size_t)(mB & 63) * Tq + (mB >> 6)) : (size_t)mB;
        float* cpa = Cb + rA * (size_t)ldc + n0;
        float* cpb = Cb + rB * (size_t)ldc + n0;
#pragma unroll
        for (int j = 0; j < TN; j++) {
            float2 f = u2f2(acc[p][j]);
            int off = j * NTX + tx;
            float va = f.x + bj[j];
            float vb = f.y + bj[j];
            if (accf) { va += cpa[off]; vb += cpb[off]; }
            cpa[off] = va;
            cpb[off] = vb;
        }
    }
}

// ---------------- small kernels ----------------------------------------------
__global__ void embed_k(const int* __restrict__ targets, const float* __restrict__ E)
{
    int m = blockIdx.x;                 // t*B + b
    int t = m >> 6, b = m & 63;
    int id = (t == 0) ? 0 : targets[b * Tq + (t - 1)];
    const float4* src = (const float4*)(E + (size_t)id * WEq);
    float4* dst = (float4*)(d_X + (size_t)m * WEq);
    dst[threadIdx.x] = src[threadIdx.x];
}

__global__ void words_k(const unsigned char* __restrict__ mask8)
{
    int b = blockIdx.x, t = threadIdx.x;
    int is8 = (mask8[1] != 0);
    int v;
    if (is8) v = mask8[b * Tq + t] ? 1 : 0;
    else     v = ((const int*)mask8)[b * Tq + t] ? 1 : 0;
#pragma unroll
    for (int o = 16; o; o >>= 1) v += __shfl_down_sync(0xffffffffu, v, o);
    __shared__ int red[8];
    if ((t & 31) == 0) red[t >> 5] = v;
    __syncthreads();
    if (t == 0) {
        int s = 0;
#pragma unroll
        for (int i = 0; i < 8; i++) s += red[i];
        d_words[b] = s;
    }
}

__global__ void h0_k(const float* __restrict__ enc)
{
    int b = blockIdx.x;
    const float4* src = (const float4*)(enc + ((size_t)b * Tq + (Tq - 1)) * Hq);
    float4* dst = (float4*)(d_H + (size_t)b * Hq);
    dst[threadIdx.x] = src[threadIdx.x];
}

__global__ void gates_k(const float* __restrict__ b_hh, int t)
{
    int idx = blockIdx.x * 256 + threadIdx.x;
    int b = idx >> 10;
    int j = idx & (Hq - 1);
    float ghr = b_hh[j], ghz = b_hh[Hq + j], ghn = b_hh[2 * Hq + j];
#pragma unroll
    for (int s = 0; s < SPLITS; s++) {
        const float* p = d_ghp + (size_t)s * Bq * G3q + (size_t)b * G3q;
        ghr += p[j]; ghz += p[Hq + j]; ghn += p[2 * Hq + j];
    }
    const float* gi = d_gi + ((size_t)t * Bq + b) * G3q;
    float r = 1.f / (1.f + expf(-(gi[j]          + ghr)));
    float z = 1.f / (1.f + expf(-(gi[Hq + j]     + ghz)));
    float n = tanhf(gi[2 * Hq + j] + r * ghn);
    float hp = d_H[(size_t)t * Bq * Hq + (size_t)b * Hq + j];
    d_H[(size_t)(t + 1) * Bq * Hq + (size_t)b * Hq + j] = (1.f - z) * n + z * hp;
}

__global__ void softmax_k()
{
    int m = blockIdx.x;                 // t*B + b
    int b = m & (Bq - 1);
    int wn = d_words[b];
    float* e = d_e + (size_t)m * Tq;
    int s = threadIdx.x;
    float v = (s < wn) ? e[s] : -3.0e38f;

    __shared__ float red[8];
    __shared__ float smax, ssum;
    float mx = v;
#pragma unroll
    for (int o = 16; o; o >>= 1) mx = fmaxf(mx, __shfl_xor_sync(0xffffffffu, mx, o));
    if ((s & 31) == 0) red[s >> 5] = mx;
    __syncthreads();
    if (s == 0) {
        float x = red[0];
#pragma unroll
        for (int i = 1; i < 8; i++) x = fmaxf(x, red[i]);
        smax = x;
    }
    __syncthreads();
    float ex = (s < wn) ? expf(v - smax) : 0.f;
    float sum = ex;
#pragma unroll
    for (int o = 16; o; o >>= 1) sum += __shfl_xor_sync(0xffffffffu, sum, o);
    if ((s & 31) == 0) red[s >> 5] = sum;
    __syncthreads();
    if (s == 0) {
        float x = 0.f;
#pragma unroll
        for (int i = 0; i < 8; i++) x += red[i];
        ssum = 1.f / x;
    }
    __syncthreads();
    e[s] = ex * ssum;
}

// ---------------- launch ------------------------------------------------------
extern "C" void kernel_launch(void* const* d_in, const int* in_sizes, int n_in,
                              void* d_out, int out_size)
{
    const float*         enc     = (const float*)d_in[0];
    const unsigned char* mask    = (const unsigned char*)d_in[1];
    const int*           targets = (const int*)d_in[2];
    const float*         E       = (const float*)d_in[3];
    const float*         W_ih    = (const float*)d_in[4];
    const float*         W_hh    = (const float*)d_in[5];
    const float*         b_ih    = (const float*)d_in[6];
    const float*         b_hh    = (const float*)d_in[7];
    const float*         W_out   = (const float*)d_in[8];
    const float*         b_out   = (const float*)d_in[9];
    float* out = (float*)d_out;

    void* p;
    cudaGetSymbolAddress(&p, d_X);   float* X   = (float*)p;
    cudaGetSymbolAddress(&p, d_gi);  float* GI  = (float*)p;
    cudaGetSymbolAddress(&p, d_H);   float* Hh  = (float*)p;
    cudaGetSymbolAddress(&p, d_ghp); float* GHP = (float*)p;
    cudaGetSymbolAddress(&p, d_e);   float* Ee  = (float*)p;
    cudaGetSymbolAddress(&p, d_ctx); float* CTX = (float*)p;

    // Phase 0
    embed_k<<<Tq * Bq, 64>>>(targets, E);
    words_k<<<Bq, 256>>>(mask);
    h0_k<<<Bq, 256>>>(enc);

    // Phase 1: gi = X @ W_ih^T + b_ih   (16384 x 3072 x 256)
    gemm2_k<128, 128, 16, 8, false><<<dim3(G3q / 128, (Tq * Bq) / 128, 1), 128>>>(
        X, nullptr, 1 << 30, W_ih, GI, WEq, WEq, WEq, G3q, 0, 0, 0, b_ih, 0, 0);

    // Phase 2: sequential GRU — per step: split-K gh GEMM (64x128 tiles,
    // TM=8/TN=8 balanced with un-dup B) + fused gates
    for (int t = 0; t < Tq; t++) {
        gemm2_k<64, 128, 8, 8, false><<<dim3(G3q / 128, 1, SPLITS), 128>>>(
            Hh + (size_t)t * Bq * Hq, nullptr, 1 << 30, W_hh, GHP, Hq / SPLITS,
            Hq, Hq, G3q,
            Hq / SPLITS, Hq / SPLITS, (long long)Bq * G3q,
            nullptr, 0, 0);
        gates_k<<<(Bq * Hq) / 256, 256>>>(b_hh, t);
    }

    // Phase 3a: e[t,b,s] = h1[t,b,:] . enc[b,s,:]
    gemm2_k<128, 128, 16, 8, false><<<dim3(Tq / 128, Tq / 128, Bq), 128>>>(
        Hh + (size_t)Bq * Hq, nullptr, 1 << 30, enc, Ee, Hq,
        Bq * Hq, Hq, Bq * Tq,
        Hq, (long long)Tq * Hq, Tq,
        nullptr, 0, 0);

    // Phase 3b: masked softmax
    softmax_k<<<Tq * Bq, Tq>>>();

    // Phase 3c: ctx[t,b,:] = alpha[t,b,:] @ enc[b]   (B n-contiguous)
    gemm2_k<128, 128, 16, 8, true><<<dim3(Hq / 128, Tq / 128, Bq), 128>>>(
        Ee, nullptr, 1 << 30, enc, CTX, Tq,
        Bq * Tq, Hq, Bq * Hq,
        Tq, (long long)Tq * Hq, Hq,
        nullptr, 0, 0);

    // Phase 4: logits = [h1 | ctx] @ W_out^T + b_out, concat K=2048,
    // written directly in (B, T, C) order (mode 1)
    gemm2_k<128, 128, 16, 8, false><<<dim3(Cq / 128, (Tq * Bq) / 128, 1), 128>>>(
        Hh + (size_t)Bq * Hq, CTX, Hq, W_out, out, 2 * Hq,
        Hq, 2 * Hq, Cq, 0, 0, 0, b_out, 0, 1);
}